// round 6
// baseline (speedup 1.0000x reference)
#include <cuda_runtime.h>
#include <cuda_fp16.h>
#include <cstdint>

#define N_NODES 100000
#define E_EDGES 1600000
#define G_GRAPHS 512
#define NB 740                              // 148 SMs x 5 blocks (guaranteed resident)
#define NTHREADS 256
#define NTILES ((N_NODES + 63) / 64)        // 1563
#define NCHUNK ((N_NODES + 255) / 256)      // 391

// ---------------- scratch (device globals) ----------------
__device__ int     g_hist[N_NODES];
__device__ int     g_offs[N_NODES];
__device__ int     g_cursor[N_NODES];
__device__ int     g_alloc;
__device__ int     g_ssrc[E_EDGES + N_NODES];
__device__ int     g_is64;

__device__ __half2 g_h1h[N_NODES * 32];     // h1 fp16, 128B/row
__device__ float   g_als1[N_NODES * 4];
__device__ float   g_ald1[N_NODES * 4];
__device__ float   g_h1e[N_NODES * 64];     // post-ELU layer1 out (fp32)
__device__ __half2 g_h2h[N_NODES * 8];      // h2 fp16, 32B/row
__device__ float   g_al2s[N_NODES];
__device__ float   g_al2d[N_NODES];
__device__ float   g_pool[G_GRAPHS * 16];
__device__ float   g_cnt[G_GRAPHS];

__device__ unsigned g_bgen = 0;
__device__ unsigned g_bcnt = 0;

// ---------------- grid barrier (all NB blocks resident) ----------------
__device__ __forceinline__ void gbar() {
    __syncthreads();
    if (threadIdx.x == 0) {
        __threadfence();
        unsigned gen = ((volatile unsigned*)&g_bgen)[0];
        if (atomicAdd(&g_bcnt, 1u) == NB - 1) {
            g_bcnt = 0;
            __threadfence();
            atomicAdd(&g_bgen, 1u);
        } else {
            while (((volatile unsigned*)&g_bgen)[0] == gen) __nanosleep(64);
        }
        __threadfence();
    }
    __syncthreads();
}

__device__ __forceinline__ void unpack8(float4 raw, float* f) {
    const __half2* h = (const __half2*)&raw;
    float2 a = __half22float2(h[0]);
    float2 b = __half22float2(h[1]);
    float2 c = __half22float2(h[2]);
    float2 d = __half22float2(h[3]);
    f[0]=a.x; f[1]=a.y; f[2]=b.x; f[3]=b.y; f[4]=c.x; f[5]=c.y; f[6]=d.x; f[7]=d.y;
}

// ---------------- the single persistent kernel ----------------
__global__ __launch_bounds__(NTHREADS, 5) void k_gat(
    const float* __restrict__ x, const void* __restrict__ ei,
    const void* __restrict__ batchp,
    const float* __restrict__ W1, const float* __restrict__ a1s,
    const float* __restrict__ a1d, const float* __restrict__ b1,
    const float* __restrict__ W2, const float* __restrict__ a2s,
    const float* __restrict__ a2d, const float* __restrict__ b2,
    const float* __restrict__ Wc, const float* __restrict__ bc,
    float* __restrict__ out) {

    __shared__ float s_w[4096];            // weights
    __shared__ float s_x[64 * 65];         // padded node tile / scan buffer
    __shared__ float s_v1[64], s_v2[64];   // attention vectors
    __shared__ int   s_base;

    const int tid  = threadIdx.x;
    const int gtid = blockIdx.x * NTHREADS + tid;

    // ========== P0: zero state + dtype detect ==========
    for (int i = gtid; i < N_NODES; i += NB * NTHREADS) g_hist[i] = 0;
    if (gtid < G_GRAPHS * 16) g_pool[gtid] = 0.f;
    if (gtid < G_GRAPHS) g_cnt[gtid] = 0.f;
    if (gtid == 0) {
        g_alloc = 0;
        const unsigned* w = (const unsigned*)ei;
        int is64 = 1;
        #pragma unroll
        for (int k = 1; k < 64; k += 2) if (w[k] != 0u) is64 = 0;
        g_is64 = is64;
    }
    gbar();

    // ========== P1: histogram of dst ==========
    {
        int is64 = g_is64;
        for (int i = gtid; i < E_EDGES; i += NB * NTHREADS) {
            int dst = is64 ? (int)((const long long*)ei)[E_EDGES + i]
                           : ((const int*)ei)[E_EDGES + i];
            atomicAdd(&g_hist[dst], 1);
        }
    }
    gbar();

    // ========== P2: segment allocation (block scan + atomic base) ==========
    {
        int* s_scan = (int*)s_x;
        for (int chunk = blockIdx.x; chunk < NCHUNK; chunk += NB) {
            int i = chunk * 256 + tid;
            int deg = (i < N_NODES) ? g_hist[i] + 1 : 0;   // +1 self loop
            s_scan[tid] = deg;
            __syncthreads();
            for (int off = 1; off < 256; off <<= 1) {
                int t = (tid >= off) ? s_scan[tid - off] : 0;
                __syncthreads();
                s_scan[tid] += t;
                __syncthreads();
            }
            if (tid == 255) s_base = atomicAdd(&g_alloc, s_scan[255]);
            __syncthreads();
            if (i < N_NODES) {
                int base = s_base + s_scan[tid] - deg;
                g_offs[i] = base;
                g_ssrc[base] = i;          // self-loop occupies slot 0
                g_cursor[i] = base + 1;
            }
            __syncthreads();
        }
    }
    gbar();

    // ========== P3a: GEMM1 h1 = x @ W1 (+ attention logits), smem-tiled ====
    {
        for (int i = tid; i < 4096; i += NTHREADS) s_w[i] = W1[i];
        if (tid < 64) { s_v1[tid] = a1s[tid]; s_v2[tid] = a1d[tid]; }
        __syncthreads();
        int node_l = tid >> 2;
        int h = tid & 3;
        for (int tile = blockIdx.x; tile < NTILES; tile += NB) {
            int t0 = tile * 64;
            // load 64x64 x tile into padded smem
            for (int i = tid; i < 1024; i += NTHREADS) {
                int row = i >> 4, c4 = i & 15;
                float4 v = make_float4(0.f, 0.f, 0.f, 0.f);
                if (t0 + row < N_NODES)
                    v = *(const float4*)(x + (size_t)(t0 + row) * 64 + c4 * 4);
                float* sp = s_x + row * 65 + c4 * 4;
                sp[0] = v.x; sp[1] = v.y; sp[2] = v.z; sp[3] = v.w;
            }
            __syncthreads();
            int n = t0 + node_l;
            float acc[16];
            #pragma unroll
            for (int j = 0; j < 16; j++) acc[j] = 0.f;
            #pragma unroll 8
            for (int k = 0; k < 64; k++) {
                float xv = s_x[node_l * 65 + k];
                #pragma unroll
                for (int j = 0; j < 16; j++)
                    acc[j] = fmaf(xv, s_w[k * 64 + h * 16 + j], acc[j]);
            }
            if (n < N_NODES) {
                float s = 0.f, d = 0.f;
                #pragma unroll
                for (int j = 0; j < 16; j++) {
                    s = fmaf(acc[j], s_v1[h * 16 + j], s);
                    d = fmaf(acc[j], s_v2[h * 16 + j], d);
                }
                g_als1[n * 4 + h] = s;
                g_ald1[n * 4 + h] = d;
                __half2* hp = g_h1h + (size_t)n * 32 + h * 8;
                #pragma unroll
                for (int j = 0; j < 8; j++)
                    hp[j] = __floats2half2_rn(acc[2*j], acc[2*j+1]);
            }
            __syncthreads();
        }
    }

    // ========== P3b: scatter edges into per-dst segments (same phase) =====
    {
        int is64 = g_is64;
        for (int i = gtid; i < E_EDGES; i += NB * NTHREADS) {
            int src, dst;
            if (is64) {
                src = (int)((const long long*)ei)[i];
                dst = (int)((const long long*)ei)[E_EDGES + i];
            } else {
                src = ((const int*)ei)[i];
                dst = ((const int*)ei)[E_EDGES + i];
            }
            int pos = atomicAdd(&g_cursor[dst], 1);
            g_ssrc[pos] = src;
        }
    }
    gbar();

    // ========== P4: layer-1 aggregation (warp/dst, 4 edges/iter) ==========
    {
        int gwid = gtid >> 5;
        int lane = tid & 31;
        int eidx = lane >> 3;             // 0..3 : edge slot within group of 4
        int j = lane & 7;                 // channel block: ch 8j..8j+7
        int head = j >> 1;
        for (int dst = gwid; dst < N_NODES; dst += NB * 8) {
            int start = g_offs[dst];
            int end   = start + g_hist[dst] + 1;
            float aldv = g_ald1[dst * 4 + head];
            float acc[8];
            #pragma unroll
            for (int i = 0; i < 8; i++) acc[i] = 0.f;
            float wsum = 0.f;

            int k = start + eidx;
            int src = 0;
            if (k < end) src = __ldg(&g_ssrc[k]);
            #pragma unroll 1
            while (k < end) {
                int cur = src;
                int kn = k + 4;
                if (kn < end) src = __ldg(&g_ssrc[kn]);    // prefetch
                float e = __ldg(&g_als1[cur * 4 + head]) + aldv;
                e = e > 0.f ? e : 0.2f * e;
                float w = __expf(e);
                float4 raw = *(const float4*)(g_h1h + (size_t)cur * 32 + 4 * j);
                float f[8];
                unpack8(raw, f);
                #pragma unroll
                for (int i = 0; i < 8; i++) acc[i] = fmaf(w, f[i], acc[i]);
                wsum += w;
                k = kn;
            }
            #pragma unroll
            for (int off = 8; off <= 16; off <<= 1) {
                #pragma unroll
                for (int i = 0; i < 8; i++)
                    acc[i] += __shfl_xor_sync(0xffffffffu, acc[i], off);
                wsum += __shfl_xor_sync(0xffffffffu, wsum, off);
            }
            if (eidx == 0) {
                float inv = 1.0f / wsum;
                float o[8];
                #pragma unroll
                for (int i = 0; i < 8; i++) {
                    float v = acc[i] * inv + __ldg(b1 + 8 * j + i);
                    o[i] = v > 0.f ? v : (__expf(v) - 1.f);   // ELU
                }
                float4* hp = (float4*)(g_h1e + (size_t)dst * 64 + 8 * j);
                hp[0] = make_float4(o[0], o[1], o[2], o[3]);
                hp[1] = make_float4(o[4], o[5], o[6], o[7]);
            }
        }
    }
    gbar();

    // ========== P5: GEMM2 h2 = h1e @ W2 (+ logits), smem-tiled ============
    {
        for (int i = tid; i < 1024; i += NTHREADS) s_w[i] = W2[i];
        if (tid < 16) { s_v1[tid] = a2s[tid]; s_v2[tid] = a2d[tid]; }
        __syncthreads();
        int node_l = tid >> 2;
        int q = tid & 3;
        for (int tile = blockIdx.x; tile < NTILES; tile += NB) {
            int t0 = tile * 64;
            for (int i = tid; i < 1024; i += NTHREADS) {
                int row = i >> 4, c4 = i & 15;
                float4 v = make_float4(0.f, 0.f, 0.f, 0.f);
                if (t0 + row < N_NODES)
                    v = *(const float4*)(g_h1e + (size_t)(t0 + row) * 64 + c4 * 4);
                float* sp = s_x + row * 65 + c4 * 4;
                sp[0] = v.x; sp[1] = v.y; sp[2] = v.z; sp[3] = v.w;
            }
            __syncthreads();
            int n = t0 + node_l;
            float acc[4];
            #pragma unroll
            for (int j = 0; j < 4; j++) acc[j] = 0.f;
            #pragma unroll 8
            for (int k = 0; k < 64; k++) {
                float xv = s_x[node_l * 65 + k];
                #pragma unroll
                for (int j = 0; j < 4; j++)
                    acc[j] = fmaf(xv, s_w[k * 16 + q * 4 + j], acc[j]);
            }
            float s = 0.f, d = 0.f;
            #pragma unroll
            for (int j = 0; j < 4; j++) {
                s = fmaf(acc[j], s_v1[q * 4 + j], s);
                d = fmaf(acc[j], s_v2[q * 4 + j], d);
            }
            s += __shfl_down_sync(0xffffffffu, s, 2, 4);
            s += __shfl_down_sync(0xffffffffu, s, 1, 4);
            d += __shfl_down_sync(0xffffffffu, d, 2, 4);
            d += __shfl_down_sync(0xffffffffu, d, 1, 4);
            if (n < N_NODES) {
                if (q == 0) { g_al2s[n] = s; g_al2d[n] = d; }
                g_h2h[(size_t)n * 8 + q * 2    ] = __floats2half2_rn(acc[0], acc[1]);
                g_h2h[(size_t)n * 8 + q * 2 + 1] = __floats2half2_rn(acc[2], acc[3]);
            }
            __syncthreads();
        }
    }
    gbar();

    // ========== P6: layer-2 agg + pooling (warp/dst, 16 edges/iter) =======
    {
        int gwid = gtid >> 5;
        int lane = tid & 31;
        int eidx = lane >> 1;             // 0..15
        int j = lane & 1;                 // channel block: ch 8j..8j+7
        for (int dst = gwid; dst < N_NODES; dst += NB * 8) {
            int start = g_offs[dst];
            int end   = start + g_hist[dst] + 1;
            float aldv = g_al2d[dst];
            float acc[8];
            #pragma unroll
            for (int i = 0; i < 8; i++) acc[i] = 0.f;
            float wsum = 0.f;

            int k = start + eidx;
            int src = 0;
            if (k < end) src = __ldg(&g_ssrc[k]);
            #pragma unroll 1
            while (k < end) {
                int cur = src;
                int kn = k + 16;
                if (kn < end) src = __ldg(&g_ssrc[kn]);
                float e = __ldg(&g_al2s[cur]) + aldv;
                e = e > 0.f ? e : 0.2f * e;
                float w = __expf(e);
                float4 raw = *(const float4*)(g_h2h + (size_t)cur * 8 + 4 * j);
                float f[8];
                unpack8(raw, f);
                #pragma unroll
                for (int i = 0; i < 8; i++) acc[i] = fmaf(w, f[i], acc[i]);
                wsum += w;
                k = kn;
            }
            #pragma unroll
            for (int off = 2; off <= 16; off <<= 1) {
                #pragma unroll
                for (int i = 0; i < 8; i++)
                    acc[i] += __shfl_xor_sync(0xffffffffu, acc[i], off);
                wsum += __shfl_xor_sync(0xffffffffu, wsum, off);
            }
            if (lane < 2) {
                float inv = 1.0f / wsum;
                int g = g_is64 ? (int)((const long long*)batchp)[dst]
                               : ((const int*)batchp)[dst];
                #pragma unroll
                for (int i = 0; i < 8; i++) {
                    float o = acc[i] * inv + __ldg(b2 + 8 * j + i);
                    o = o > 0.f ? o : (__expf(o) - 1.f);      // ELU
                    atomicAdd(&g_pool[g * 16 + 8 * j + i], o);
                }
                if (lane == 0) atomicAdd(&g_cnt[g], 1.0f);
            }
        }
    }
    gbar();

    // ========== P7: final mean + linear head ==========
    if (blockIdx.x == 0) {
        for (int g = tid; g < G_GRAPHS; g += NTHREADS) {
            float inv = 1.0f / fmaxf(g_cnt[g], 1.0f);
            float s = 0.f;
            #pragma unroll
            for (int c = 0; c < 16; c++)
                s = fmaf(g_pool[g * 16 + c] * inv, Wc[c], s);
            out[g] = s + bc[0];
        }
    }
}

// ---------------- launch ----------------
extern "C" void kernel_launch(void* const* d_in, const int* in_sizes, int n_in,
                              void* d_out, int out_size) {
    const float* x    = (const float*)d_in[0];
    const void*  ei   = d_in[1];
    const void*  batch = d_in[2];
    const float* W1   = (const float*)d_in[3];
    const float* a1s  = (const float*)d_in[4];
    const float* a1d  = (const float*)d_in[5];
    const float* b1   = (const float*)d_in[6];
    const float* W2   = (const float*)d_in[7];
    const float* a2s  = (const float*)d_in[8];
    const float* a2d  = (const float*)d_in[9];
    const float* b2   = (const float*)d_in[10];
    const float* Wc   = (const float*)d_in[11];
    const float* bc   = (const float*)d_in[12];
    float* out = (float*)d_out;

    k_gat<<<NB, NTHREADS>>>(x, ei, batch, W1, a1s, a1d, b1,
                            W2, a2s, a2d, b2, Wc, bc, out);
}

// round 8
// speedup vs baseline: 1.0968x; 1.0968x over previous
#include <cuda_runtime.h>
#include <cuda_fp16.h>
#include <cstdint>

#define N_NODES 100000
#define E_EDGES 1600000
#define G_GRAPHS 512
#define NB_ALLOC ((N_NODES + 255) / 256)      // 391

// ---------------- scratch (device globals; zero-initialized at load) ------
__device__ int     g_hist[N_NODES];
__device__ int     g_offs[N_NODES];
__device__ int     g_cursor[N_NODES];
__device__ int     g_alloc;
__device__ int     g_ssrc[E_EDGES + N_NODES];
__device__ int     g_is64;

__device__ __half2 g_h1h[N_NODES * 32];        // h1 fp16, 128B/row
__device__ float   g_als1[N_NODES * 4];
__device__ float   g_ald1[N_NODES * 4];
__device__ float   g_h1e[N_NODES * 64];        // post-ELU layer1 out (fp32)
__device__ __half2 g_h2h[N_NODES * 8];         // h2 fp16, 32B/row
__device__ float   g_al2s[N_NODES];
__device__ float   g_al2d[N_NODES];
__device__ float   g_pool[G_GRAPHS * 16];
__device__ float   g_cnt[G_GRAPHS];

__device__ __forceinline__ void unpack8(float4 raw, float* f) {
    const __half2* h = (const __half2*)&raw;
    float2 a = __half22float2(h[0]);
    float2 b = __half22float2(h[1]);
    float2 c = __half22float2(h[2]);
    float2 d = __half22float2(h[3]);
    f[0]=a.x; f[1]=a.y; f[2]=b.x; f[3]=b.y; f[4]=c.x; f[5]=c.y; f[6]=d.x; f[7]=d.y;
}

// ---------------- K1: histogram of dst (+ dtype detect); zero-smem-light --
__global__ __launch_bounds__(256) void k_hist(const void* __restrict__ ei) {
    __shared__ int s_is64;
    if (threadIdx.x == 0) {
        const unsigned* w = (const unsigned*)ei;
        int is64 = 1;
        #pragma unroll
        for (int k = 1; k < 64; k += 2) if (w[k] != 0u) is64 = 0;
        s_is64 = is64;
        if (blockIdx.x == 0) g_is64 = is64;
    }
    __syncthreads();
    int i = blockIdx.x * 256 + threadIdx.x;
    if (i >= E_EDGES) return;
    int dst = s_is64 ? (int)((const long long*)ei)[E_EDGES + i]
                     : ((const int*)ei)[E_EDGES + i];
    atomicAdd(&g_hist[dst], 1);
}

// ---------------- K2: segment allocation (block scan + one atomic) --------
__global__ __launch_bounds__(256) void k_alloc() {
    __shared__ int sh[256];
    __shared__ int sbase;
    int i = blockIdx.x * 256 + threadIdx.x;
    int deg = (i < N_NODES) ? g_hist[i] + 1 : 0;   // +1 self loop
    sh[threadIdx.x] = deg;
    __syncthreads();
    for (int off = 1; off < 256; off <<= 1) {
        int t = (threadIdx.x >= off) ? sh[threadIdx.x - off] : 0;
        __syncthreads();
        sh[threadIdx.x] += t;
        __syncthreads();
    }
    if (threadIdx.x == 255) sbase = atomicAdd(&g_alloc, sh[255]);
    __syncthreads();
    if (i < N_NODES) {
        int base = sbase + sh[threadIdx.x] - deg;
        g_offs[i] = base;
        g_ssrc[base] = i;          // self-loop occupies slot 0
        g_cursor[i] = base + 1;
    }
}

// ---------------- K3: scatter edges by dst; zero smem, full occ -----------
__global__ __launch_bounds__(256) void k_scatter(const void* __restrict__ ei) {
    int i = blockIdx.x * 256 + threadIdx.x;
    if (i >= E_EDGES) return;
    int src, dst;
    if (g_is64) {
        src = (int)((const long long*)ei)[i];
        dst = (int)((const long long*)ei)[E_EDGES + i];
    } else {
        src = ((const int*)ei)[i];
        dst = ((const int*)ei)[E_EDGES + i];
    }
    int pos = atomicAdd(&g_cursor[dst], 1);
    g_ssrc[pos] = src;
}

// ---------------- K4: GEMM1 h1 = x @ W1 (+ logits); w-loads broadcast -----
__global__ __launch_bounds__(128) void k_gemm1(
    const float* __restrict__ x, const float* __restrict__ W1,
    const float* __restrict__ a1s, const float* __restrict__ a1d) {
    __shared__ float ws[64 * 64];
    __shared__ float sas[64], sad[64];
    for (int i = threadIdx.x; i < 4096; i += 128) ws[i] = W1[i];
    if (threadIdx.x < 64) { sas[threadIdx.x] = a1s[threadIdx.x]; sad[threadIdx.x] = a1d[threadIdx.x]; }
    __syncthreads();
    int n = blockIdx.x * 128 + threadIdx.x;
    if (n >= N_NODES) return;

    float xr[64];
    const float4* xp = (const float4*)(x + (size_t)n * 64);
    #pragma unroll
    for (int i = 0; i < 16; i++) {
        float4 v = xp[i];
        xr[4*i] = v.x; xr[4*i+1] = v.y; xr[4*i+2] = v.z; xr[4*i+3] = v.w;
    }
    #pragma unroll 1
    for (int h = 0; h < 4; h++) {
        float acc[16];
        #pragma unroll
        for (int j = 0; j < 16; j++) acc[j] = 0.f;
        #pragma unroll
        for (int k = 0; k < 64; k++) {
            float xv = xr[k];
            #pragma unroll
            for (int j = 0; j < 16; j++)
                acc[j] = fmaf(xv, ws[k * 64 + h * 16 + j], acc[j]);
        }
        float s = 0.f, d = 0.f;
        #pragma unroll
        for (int j = 0; j < 16; j++) {
            s = fmaf(acc[j], sas[h * 16 + j], s);
            d = fmaf(acc[j], sad[h * 16 + j], d);
        }
        __half2* hp = g_h1h + (size_t)n * 32 + h * 8;
        #pragma unroll
        for (int j = 0; j < 8; j++)
            hp[j] = __floats2half2_rn(acc[2*j], acc[2*j+1]);
        g_als1[n * 4 + h] = s;
        g_ald1[n * 4 + h] = d;
    }
}

// ---------------- K5: layer-1 aggregation (warp/dst, 4 edges/iter) --------
__global__ __launch_bounds__(256) void k_agg1(const float* __restrict__ b1) {
    int wid = (blockIdx.x * blockDim.x + threadIdx.x) >> 5;
    int lane = threadIdx.x & 31;
    if (wid >= N_NODES) return;
    int eidx = lane >> 3;                 // 0..3 : edge slot within group of 4
    int j = lane & 7;                     // channel block: ch 8j..8j+7
    int head = j >> 1;
    int dst = wid;
    int start = g_offs[dst];
    int end   = start + g_hist[dst] + 1;
    float aldv = g_ald1[dst * 4 + head];
    float acc[8];
    #pragma unroll
    for (int i = 0; i < 8; i++) acc[i] = 0.f;
    float wsum = 0.f;

    int k = start + eidx;
    int src = 0;
    if (k < end) src = __ldg(&g_ssrc[k]);
    #pragma unroll 1
    while (k < end) {
        int cur = src;
        int kn = k + 4;
        if (kn < end) src = __ldg(&g_ssrc[kn]);   // prefetch next index
        float e = __ldg(&g_als1[cur * 4 + head]) + aldv;
        e = e > 0.f ? e : 0.2f * e;
        float w = __expf(e);
        float4 raw = *(const float4*)(g_h1h + (size_t)cur * 32 + 4 * j);
        float f[8];
        unpack8(raw, f);
        #pragma unroll
        for (int i = 0; i < 8; i++) acc[i] = fmaf(w, f[i], acc[i]);
        wsum += w;
        k = kn;
    }
    #pragma unroll
    for (int off = 8; off <= 16; off <<= 1) {
        #pragma unroll
        for (int i = 0; i < 8; i++) acc[i] += __shfl_xor_sync(0xffffffffu, acc[i], off);
        wsum += __shfl_xor_sync(0xffffffffu, wsum, off);
    }
    if (eidx == 0) {
        float inv = 1.0f / wsum;
        float o[8];
        #pragma unroll
        for (int i = 0; i < 8; i++) {
            float v = acc[i] * inv + __ldg(b1 + 8 * j + i);
            o[i] = v > 0.f ? v : (__expf(v) - 1.f);        // ELU
        }
        float4* hp = (float4*)(g_h1e + (size_t)dst * 64 + 8 * j);
        hp[0] = make_float4(o[0], o[1], o[2], o[3]);
        hp[1] = make_float4(o[4], o[5], o[6], o[7]);
    }
}

// ---------------- K6: GEMM2 h2 = h1e @ W2 (+ logits) ----------------------
__global__ __launch_bounds__(128) void k_gemm2(
    const float* __restrict__ W2,
    const float* __restrict__ a2s, const float* __restrict__ a2d) {
    __shared__ float ws[64 * 16];
    __shared__ float s2s[16], s2d[16];
    for (int i = threadIdx.x; i < 1024; i += 128) ws[i] = W2[i];
    if (threadIdx.x < 16) { s2s[threadIdx.x] = a2s[threadIdx.x]; s2d[threadIdx.x] = a2d[threadIdx.x]; }
    __syncthreads();
    int n = blockIdx.x * 128 + threadIdx.x;
    if (n >= N_NODES) return;

    float v[64];
    const float4* vp = (const float4*)(g_h1e + (size_t)n * 64);
    #pragma unroll
    for (int i = 0; i < 16; i++) {
        float4 t = vp[i];
        v[4*i] = t.x; v[4*i+1] = t.y; v[4*i+2] = t.z; v[4*i+3] = t.w;
    }
    float acc[16];
    #pragma unroll
    for (int j = 0; j < 16; j++) acc[j] = 0.f;
    #pragma unroll
    for (int k = 0; k < 64; k++) {
        float xv = v[k];
        #pragma unroll
        for (int j = 0; j < 16; j++)
            acc[j] = fmaf(xv, ws[k * 16 + j], acc[j]);
    }
    float s = 0.f, d = 0.f;
    #pragma unroll
    for (int j = 0; j < 16; j++) {
        s = fmaf(acc[j], s2s[j], s);
        d = fmaf(acc[j], s2d[j], d);
    }
    __half2* hp = g_h2h + (size_t)n * 8;
    #pragma unroll
    for (int j = 0; j < 8; j++)
        hp[j] = __floats2half2_rn(acc[2*j], acc[2*j+1]);
    g_al2s[n] = s;
    g_al2d[n] = d;
}

// ---------------- K7: layer-2 agg + pooling (warp/dst, 16 edges/iter) -----
__global__ __launch_bounds__(256) void k_agg2(
    const float* __restrict__ b2, const void* __restrict__ batchp) {
    int wid = (blockIdx.x * blockDim.x + threadIdx.x) >> 5;
    int lane = threadIdx.x & 31;
    if (wid >= N_NODES) return;
    int eidx = lane >> 1;                 // 0..15 : edge slot within group of 16
    int j = lane & 1;                     // channel block: ch 8j..8j+7
    int dst = wid;
    int start = g_offs[dst];
    int end   = start + g_hist[dst] + 1;
    float aldv = g_al2d[dst];
    float acc[8];
    #pragma unroll
    for (int i = 0; i < 8; i++) acc[i] = 0.f;
    float wsum = 0.f;

    int k = start + eidx;
    int src = 0;
    if (k < end) src = __ldg(&g_ssrc[k]);
    #pragma unroll 1
    while (k < end) {
        int cur = src;
        int kn = k + 16;
        if (kn < end) src = __ldg(&g_ssrc[kn]);
        float e = __ldg(&g_al2s[cur]) + aldv;
        e = e > 0.f ? e : 0.2f * e;
        float w = __expf(e);
        float4 raw = *(const float4*)(g_h2h + (size_t)cur * 8 + 4 * j);
        float f[8];
        unpack8(raw, f);
        #pragma unroll
        for (int i = 0; i < 8; i++) acc[i] = fmaf(w, f[i], acc[i]);
        wsum += w;
        k = kn;
    }
    #pragma unroll
    for (int off = 2; off <= 16; off <<= 1) {
        #pragma unroll
        for (int i = 0; i < 8; i++) acc[i] += __shfl_xor_sync(0xffffffffu, acc[i], off);
        wsum += __shfl_xor_sync(0xffffffffu, wsum, off);
    }
    if (lane < 2) {
        float inv = 1.0f / wsum;
        int g = g_is64 ? (int)((const long long*)batchp)[dst]
                       : ((const int*)batchp)[dst];
        #pragma unroll
        for (int i = 0; i < 8; i++) {
            float o = acc[i] * inv + __ldg(b2 + 8 * j + i);
            o = o > 0.f ? o : (__expf(o) - 1.f);          // ELU
            atomicAdd(&g_pool[g * 16 + 8 * j + i], o);
        }
        if (lane == 0) {
            atomicAdd(&g_cnt[g], 1.0f);
            g_hist[dst] = 0;                               // reset for next call
        }
    }
}

// ---------------- K8: final mean + linear head (+ state reset) ------------
__global__ void k_final(const float* __restrict__ Wc, const float* __restrict__ bc,
                        float* __restrict__ out) {
    int g = threadIdx.x;
    if (g >= G_GRAPHS) return;
    float inv = 1.0f / fmaxf(g_cnt[g], 1.0f);
    float s = 0.f;
    #pragma unroll
    for (int c = 0; c < 16; c++) {
        s = fmaf(g_pool[g * 16 + c] * inv, Wc[c], s);
        g_pool[g * 16 + c] = 0.f;              // reset for next call
    }
    out[g] = s + bc[0];
    g_cnt[g] = 0.f;
    if (g == 0) g_alloc = 0;
}

// ---------------- launch ----------------
extern "C" void kernel_launch(void* const* d_in, const int* in_sizes, int n_in,
                              void* d_out, int out_size) {
    const float* x    = (const float*)d_in[0];
    const void*  ei   = d_in[1];
    const void*  batch = d_in[2];
    const float* W1   = (const float*)d_in[3];
    const float* a1s  = (const float*)d_in[4];
    const float* a1d  = (const float*)d_in[5];
    const float* b1   = (const float*)d_in[6];
    const float* W2   = (const float*)d_in[7];
    const float* a2s  = (const float*)d_in[8];
    const float* a2d  = (const float*)d_in[9];
    const float* b2   = (const float*)d_in[10];
    const float* Wc   = (const float*)d_in[11];
    const float* bc   = (const float*)d_in[12];
    float* out = (float*)d_out;

    k_hist<<<(E_EDGES + 255) / 256, 256>>>(ei);
    k_alloc<<<NB_ALLOC, 256>>>();
    k_scatter<<<(E_EDGES + 255) / 256, 256>>>(ei);
    k_gemm1<<<(N_NODES + 127) / 128, 128>>>(x, W1, a1s, a1d);
    k_agg1<<<(N_NODES * 32 + 255) / 256, 256>>>(b1);
    k_gemm2<<<(N_NODES + 127) / 128, 128>>>(W2, a2s, a2d);
    k_agg2<<<(N_NODES * 32 + 255) / 256, 256>>>(b2, batch);
    k_final<<<1, 512>>>(Wc, bc, out);
}

// round 9
// speedup vs baseline: 1.1814x; 1.0771x over previous
#include <cuda_runtime.h>
#include <cuda_fp16.h>
#include <cstdint>

#define N_NODES 100000
#define E_EDGES 1600000
#define G_GRAPHS 512
#define NB_ALLOC ((N_NODES + 255) / 256)      // 391

// ---------------- scratch (device globals; zero-initialized at load) ------
__device__ int     g_hist[N_NODES];
__device__ int     g_offs[N_NODES];
__device__ int     g_cursor[N_NODES];
__device__ int     g_alloc;
__device__ int     g_ssrc[E_EDGES + N_NODES];
__device__ int     g_is64;

__device__ __half2 g_h1h[N_NODES * 32];        // h1 fp16, 128B/row
__device__ float   g_als1[N_NODES * 4];
__device__ float   g_ald1[N_NODES * 4];
__device__ __half2 g_h1eh[N_NODES * 32];       // post-ELU layer1 out, fp16
__device__ __half2 g_h2h[N_NODES * 8];         // h2 fp16, 32B/row
__device__ float   g_al2s[N_NODES];
__device__ float   g_al2d[N_NODES];
__device__ float   g_pool[G_GRAPHS * 16];
__device__ float   g_cnt[G_GRAPHS];

__device__ __forceinline__ void unpack8(float4 raw, float* f) {
    const __half2* h = (const __half2*)&raw;
    float2 a = __half22float2(h[0]);
    float2 b = __half22float2(h[1]);
    float2 c = __half22float2(h[2]);
    float2 d = __half22float2(h[3]);
    f[0]=a.x; f[1]=a.y; f[2]=b.x; f[3]=b.y; f[4]=c.x; f[5]=c.y; f[6]=d.x; f[7]=d.y;
}

// ---------------- K1: histogram of dst (+ dtype detect) ----------------
__global__ __launch_bounds__(256) void k_hist(const void* __restrict__ ei) {
    __shared__ int s_is64;
    if (threadIdx.x == 0) {
        const unsigned* w = (const unsigned*)ei;
        int is64 = 1;
        #pragma unroll
        for (int k = 1; k < 64; k += 2) if (w[k] != 0u) is64 = 0;
        s_is64 = is64;
        if (blockIdx.x == 0) g_is64 = is64;
    }
    __syncthreads();
    int i = blockIdx.x * 256 + threadIdx.x;
    if (i >= E_EDGES) return;
    int dst = s_is64 ? (int)((const long long*)ei)[E_EDGES + i]
                     : ((const int*)ei)[E_EDGES + i];
    atomicAdd(&g_hist[dst], 1);
}

// ---------------- K2: segment allocation (block scan + one atomic) --------
__global__ __launch_bounds__(256) void k_alloc() {
    __shared__ int sh[256];
    __shared__ int sbase;
    int i = blockIdx.x * 256 + threadIdx.x;
    int deg = (i < N_NODES) ? g_hist[i] + 1 : 0;   // +1 self loop
    sh[threadIdx.x] = deg;
    __syncthreads();
    for (int off = 1; off < 256; off <<= 1) {
        int t = (threadIdx.x >= off) ? sh[threadIdx.x - off] : 0;
        __syncthreads();
        sh[threadIdx.x] += t;
        __syncthreads();
    }
    if (threadIdx.x == 255) sbase = atomicAdd(&g_alloc, sh[255]);
    __syncthreads();
    if (i < N_NODES) {
        int base = sbase + sh[threadIdx.x] - deg;
        g_offs[i] = base;
        g_ssrc[base] = i;          // self-loop occupies slot 0
        g_cursor[i] = base + 1;
    }
}

// ---------------- K3: scatter edges by dst ----------------
__global__ __launch_bounds__(256) void k_scatter(const void* __restrict__ ei) {
    int i = blockIdx.x * 256 + threadIdx.x;
    if (i >= E_EDGES) return;
    int src, dst;
    if (g_is64) {
        src = (int)((const long long*)ei)[i];
        dst = (int)((const long long*)ei)[E_EDGES + i];
    } else {
        src = ((const int*)ei)[i];
        dst = ((const int*)ei)[E_EDGES + i];
    }
    int pos = atomicAdd(&g_cursor[dst], 1);
    g_ssrc[pos] = src;
}

// ---------------- K4: GEMM1 h1 = x @ W1 (+ logits) -- unchanged -----------
__global__ __launch_bounds__(128) void k_gemm1(
    const float* __restrict__ x, const float* __restrict__ W1,
    const float* __restrict__ a1s, const float* __restrict__ a1d) {
    __shared__ float ws[64 * 64];
    __shared__ float sas[64], sad[64];
    for (int i = threadIdx.x; i < 4096; i += 128) ws[i] = W1[i];
    if (threadIdx.x < 64) { sas[threadIdx.x] = a1s[threadIdx.x]; sad[threadIdx.x] = a1d[threadIdx.x]; }
    __syncthreads();
    int n = blockIdx.x * 128 + threadIdx.x;
    if (n >= N_NODES) return;

    float xr[64];
    const float4* xp = (const float4*)(x + (size_t)n * 64);
    #pragma unroll
    for (int i = 0; i < 16; i++) {
        float4 v = xp[i];
        xr[4*i] = v.x; xr[4*i+1] = v.y; xr[4*i+2] = v.z; xr[4*i+3] = v.w;
    }
    #pragma unroll 1
    for (int h = 0; h < 4; h++) {
        float acc[16];
        #pragma unroll
        for (int j = 0; j < 16; j++) acc[j] = 0.f;
        #pragma unroll
        for (int k = 0; k < 64; k++) {
            float xv = xr[k];
            #pragma unroll
            for (int j = 0; j < 16; j++)
                acc[j] = fmaf(xv, ws[k * 64 + h * 16 + j], acc[j]);
        }
        float s = 0.f, d = 0.f;
        #pragma unroll
        for (int j = 0; j < 16; j++) {
            s = fmaf(acc[j], sas[h * 16 + j], s);
            d = fmaf(acc[j], sad[h * 16 + j], d);
        }
        __half2* hp = g_h1h + (size_t)n * 32 + h * 8;
        #pragma unroll
        for (int j = 0; j < 8; j++)
            hp[j] = __floats2half2_rn(acc[2*j], acc[2*j+1]);
        g_als1[n * 4 + h] = s;
        g_ald1[n * 4 + h] = d;
    }
}

// ---------------- K5: layer-1 aggregation (warp/dst, 4 edges/iter) --------
__global__ __launch_bounds__(256) void k_agg1(const float* __restrict__ b1) {
    int wid = (blockIdx.x * blockDim.x + threadIdx.x) >> 5;
    int lane = threadIdx.x & 31;
    if (wid >= N_NODES) return;
    int eidx = lane >> 3;                 // 0..3 : edge slot within group of 4
    int j = lane & 7;                     // channel block: ch 8j..8j+7
    int head = j >> 1;
    int dst = wid;
    int start = g_offs[dst];
    int end   = start + g_hist[dst] + 1;
    float aldv = g_ald1[dst * 4 + head];
    float acc[8];
    #pragma unroll
    for (int i = 0; i < 8; i++) acc[i] = 0.f;
    float wsum = 0.f;

    int k = start + eidx;
    int src = 0;
    if (k < end) src = __ldg(&g_ssrc[k]);
    #pragma unroll 1
    while (k < end) {
        int cur = src;
        int kn = k + 4;
        if (kn < end) src = __ldg(&g_ssrc[kn]);   // prefetch next index
        float e = __ldg(&g_als1[cur * 4 + head]) + aldv;
        e = e > 0.f ? e : 0.2f * e;
        float w = __expf(e);
        float4 raw = *(const float4*)(g_h1h + (size_t)cur * 32 + 4 * j);
        float f[8];
        unpack8(raw, f);
        #pragma unroll
        for (int i = 0; i < 8; i++) acc[i] = fmaf(w, f[i], acc[i]);
        wsum += w;
        k = kn;
    }
    #pragma unroll
    for (int off = 8; off <= 16; off <<= 1) {
        #pragma unroll
        for (int i = 0; i < 8; i++) acc[i] += __shfl_xor_sync(0xffffffffu, acc[i], off);
        wsum += __shfl_xor_sync(0xffffffffu, wsum, off);
    }
    if (eidx == 0) {
        float inv = 1.0f / wsum;
        float o[8];
        #pragma unroll
        for (int i = 0; i < 8; i++) {
            float v = acc[i] * inv + __ldg(b1 + 8 * j + i);
            o[i] = v > 0.f ? v : (__expf(v) - 1.f);        // ELU
        }
        __half2 p[4];
        #pragma unroll
        for (int i = 0; i < 4; i++) p[i] = __floats2half2_rn(o[2*i], o[2*i+1]);
        *(float4*)(g_h1eh + (size_t)dst * 32 + 4 * j) = *(float4*)p;
    }
}

// ---------------- K6: GEMM2 h2 = h1e @ W2 (+ logits); fp16 in, f4 weights -
__global__ __launch_bounds__(128) void k_gemm2(
    const float* __restrict__ W2,
    const float* __restrict__ a2s, const float* __restrict__ a2d) {
    __shared__ float ws[64 * 16];
    __shared__ float s2s[16], s2d[16];
    for (int i = threadIdx.x; i < 1024; i += 128) ws[i] = W2[i];
    if (threadIdx.x < 16) { s2s[threadIdx.x] = a2s[threadIdx.x]; s2d[threadIdx.x] = a2d[threadIdx.x]; }
    __syncthreads();
    int n = blockIdx.x * 128 + threadIdx.x;
    if (n >= N_NODES) return;

    float v[64];
    const float4* vp = (const float4*)(g_h1eh + (size_t)n * 32);
    #pragma unroll
    for (int i = 0; i < 8; i++) {
        float4 raw = vp[i];
        unpack8(raw, v + 8 * i);
    }
    float acc[16];
    #pragma unroll
    for (int j = 0; j < 16; j++) acc[j] = 0.f;
    #pragma unroll
    for (int k = 0; k < 64; k++) {
        float xv = v[k];
        const float4* wp = (const float4*)&ws[k * 16];
        #pragma unroll
        for (int q = 0; q < 4; q++) {
            float4 w4 = wp[q];
            acc[4*q  ] = fmaf(xv, w4.x, acc[4*q  ]);
            acc[4*q+1] = fmaf(xv, w4.y, acc[4*q+1]);
            acc[4*q+2] = fmaf(xv, w4.z, acc[4*q+2]);
            acc[4*q+3] = fmaf(xv, w4.w, acc[4*q+3]);
        }
    }
    float s = 0.f, d = 0.f;
    #pragma unroll
    for (int j = 0; j < 16; j++) {
        s = fmaf(acc[j], s2s[j], s);
        d = fmaf(acc[j], s2d[j], d);
    }
    __half2* hp = g_h2h + (size_t)n * 8;
    #pragma unroll
    for (int j = 0; j < 8; j++)
        hp[j] = __floats2half2_rn(acc[2*j], acc[2*j+1]);
    g_al2s[n] = s;
    g_al2d[n] = d;
}

// ---------------- K7: layer-2 agg + pooling (warp/dst, 16 edges/iter) -----
__global__ __launch_bounds__(256) void k_agg2(
    const float* __restrict__ b2, const void* __restrict__ batchp) {
    int wid = (blockIdx.x * blockDim.x + threadIdx.x) >> 5;
    int lane = threadIdx.x & 31;
    if (wid >= N_NODES) return;
    int eidx = lane >> 1;                 // 0..15 : edge slot within group of 16
    int j = lane & 1;                     // channel block: ch 8j..8j+7
    int dst = wid;
    int start = g_offs[dst];
    int end   = start + g_hist[dst] + 1;
    float aldv = g_al2d[dst];
    float acc[8];
    #pragma unroll
    for (int i = 0; i < 8; i++) acc[i] = 0.f;
    float wsum = 0.f;

    int k = start + eidx;
    int src = 0;
    if (k < end) src = __ldg(&g_ssrc[k]);
    #pragma unroll 1
    while (k < end) {
        int cur = src;
        int kn = k + 16;
        if (kn < end) src = __ldg(&g_ssrc[kn]);
        float e = __ldg(&g_al2s[cur]) + aldv;
        e = e > 0.f ? e : 0.2f * e;
        float w = __expf(e);
        float4 raw = *(const float4*)(g_h2h + (size_t)cur * 8 + 4 * j);
        float f[8];
        unpack8(raw, f);
        #pragma unroll
        for (int i = 0; i < 8; i++) acc[i] = fmaf(w, f[i], acc[i]);
        wsum += w;
        k = kn;
    }
    #pragma unroll
    for (int off = 2; off <= 16; off <<= 1) {
        #pragma unroll
        for (int i = 0; i < 8; i++) acc[i] += __shfl_xor_sync(0xffffffffu, acc[i], off);
        wsum += __shfl_xor_sync(0xffffffffu, wsum, off);
    }
    if (lane < 2) {
        float inv = 1.0f / wsum;
        int g = g_is64 ? (int)((const long long*)batchp)[dst]
                       : ((const int*)batchp)[dst];
        #pragma unroll
        for (int i = 0; i < 8; i++) {
            float o = acc[i] * inv + __ldg(b2 + 8 * j + i);
            o = o > 0.f ? o : (__expf(o) - 1.f);          // ELU
            atomicAdd(&g_pool[g * 16 + 8 * j + i], o);
        }
        if (lane == 0) {
            atomicAdd(&g_cnt[g], 1.0f);
            g_hist[dst] = 0;                               // reset for next call
        }
    }
}

// ---------------- K8: final mean + linear head (+ state reset) ------------
__global__ void k_final(const float* __restrict__ Wc, const float* __restrict__ bc,
                        float* __restrict__ out) {
    int g = threadIdx.x;
    if (g >= G_GRAPHS) return;
    float inv = 1.0f / fmaxf(g_cnt[g], 1.0f);
    float s = 0.f;
    #pragma unroll
    for (int c = 0; c < 16; c++) {
        s = fmaf(g_pool[g * 16 + c] * inv, Wc[c], s);
        g_pool[g * 16 + c] = 0.f;              // reset for next call
    }
    out[g] = s + bc[0];
    g_cnt[g] = 0.f;
    if (g == 0) g_alloc = 0;
}

// ---------------- launch: fork-join overlap of gemm1 with edge prep -------
static cudaStream_t s_side = 0;
static cudaEvent_t  e_fork = 0, e_join = 0;

extern "C" void kernel_launch(void* const* d_in, const int* in_sizes, int n_in,
                              void* d_out, int out_size) {
    const float* x    = (const float*)d_in[0];
    const void*  ei   = d_in[1];
    const void*  batch = d_in[2];
    const float* W1   = (const float*)d_in[3];
    const float* a1s  = (const float*)d_in[4];
    const float* a1d  = (const float*)d_in[5];
    const float* b1   = (const float*)d_in[6];
    const float* W2   = (const float*)d_in[7];
    const float* a2s  = (const float*)d_in[8];
    const float* a2d  = (const float*)d_in[9];
    const float* b2   = (const float*)d_in[10];
    const float* Wc   = (const float*)d_in[11];
    const float* bc   = (const float*)d_in[12];
    float* out = (float*)d_out;

    if (!s_side) {
        cudaStreamCreateWithFlags(&s_side, cudaStreamNonBlocking);
        cudaEventCreateWithFlags(&e_fork, cudaEventDisableTiming);
        cudaEventCreateWithFlags(&e_join, cudaEventDisableTiming);
    }

    // fork: gemm1 on side stream, edge prep on main stream (independent)
    cudaEventRecord(e_fork, 0);
    cudaStreamWaitEvent(s_side, e_fork, 0);
    k_gemm1<<<(N_NODES + 127) / 128, 128, 0, s_side>>>(x, W1, a1s, a1d);
    cudaEventRecord(e_join, s_side);

    k_hist<<<(E_EDGES + 255) / 256, 256>>>(ei);
    k_alloc<<<NB_ALLOC, 256>>>();
    k_scatter<<<(E_EDGES + 255) / 256, 256>>>(ei);

    // join: agg1 needs both gemm1 outputs and scattered edges
    cudaStreamWaitEvent(0, e_join, 0);
    k_agg1<<<(N_NODES * 32 + 255) / 256, 256>>>(b1);
    k_gemm2<<<(N_NODES + 127) / 128, 128>>>(W2, a2s, a2d);
    k_agg2<<<(N_NODES * 32 + 255) / 256, 256>>>(b2, batch);
    k_final<<<1, 512>>>(Wc, bc, out);
}